// round 1
// baseline (speedup 1.0000x reference)
#include <cuda_runtime.h>

#define B 4
#define S 2048
#define E 1024
#define H 16
#define D 64

#define BM 128   // q rows per block
#define BN 64    // k rows per tile

// scratch for attention output [B, S, E] (layout identical to q)
__device__ float g_attn[(size_t)B * S * E];

// ---------------------------------------------------------------------------
// Flash attention: one thread = one q row. K/V tiles in dynamic smem,
// per-thread score row in padded smem.
// ---------------------------------------------------------------------------
__global__ void __launch_bounds__(BM, 2)
attn_kernel(const float* __restrict__ q,
            const float* __restrict__ k,
            const float* __restrict__ v)
{
    extern __shared__ float sm[];
    float* Ksh = sm;                 // [BN][D]   4096 floats
    float* Vsh = sm + BN * D;        // [BN][D]   4096 floats
    float* Ssh = sm + 2 * BN * D;    // [BM][65]  8320 floats (padded rows)

    const int tid = threadIdx.x;
    const int qt  = blockIdx.x;
    const int h   = blockIdx.y;
    const int b   = blockIdx.z;
    const int r   = qt * BM + tid;

    const float scale = 0.125f;      // 1/sqrt(64)

    // load q row into registers, pre-scaled
    const float* qrow = q + ((size_t)(b * S + r)) * E + h * D;
    float qreg[D];
#pragma unroll
    for (int c = 0; c < D; c += 4) {
        float4 t = *(const float4*)&qrow[c];
        qreg[c+0] = t.x * scale;
        qreg[c+1] = t.y * scale;
        qreg[c+2] = t.z * scale;
        qreg[c+3] = t.w * scale;
    }

    float o[D];
#pragma unroll
    for (int c = 0; c < D; c++) o[c] = 0.0f;
    float m = -1e30f;
    float l = 0.0f;

    const float* kbase = k + ((size_t)b * S) * E + h * D;
    const float* vbase = v + ((size_t)b * S) * E + h * D;
    float* srow_sh = &Ssh[tid * 65];

    for (int kt = 0; kt < S / BN; kt++) {
        __syncthreads();   // protect smem from previous iteration's readers
        // cooperative load of K/V tiles: 1024 float4 each, 8 per thread
#pragma unroll
        for (int i = 0; i < 8; i++) {
            int f = i * BM + tid;
            int j = f >> 4;              // tile row 0..63
            int c = (f & 15) << 2;       // col 0,4,..,60
            size_t goff = (size_t)(kt * BN + j) * E + c;
            *(float4*)&Ksh[j * D + c] = *(const float4*)&kbase[goff];
            *(float4*)&Vsh[j * D + c] = *(const float4*)&vbase[goff];
        }
        __syncthreads();

        // pass 1: scores + running max
        float mnew = m;
#pragma unroll 2
        for (int j = 0; j < BN; j++) {
            const float* krow = &Ksh[j * D];
            float a0 = 0.f, a1 = 0.f, a2 = 0.f, a3 = 0.f;
#pragma unroll
            for (int c = 0; c < D; c += 4) {
                float4 kv = *(const float4*)&krow[c];
                a0 = fmaf(qreg[c+0], kv.x, a0);
                a1 = fmaf(qreg[c+1], kv.y, a1);
                a2 = fmaf(qreg[c+2], kv.z, a2);
                a3 = fmaf(qreg[c+3], kv.w, a3);
            }
            float sj = (a0 + a1) + (a2 + a3);
            srow_sh[j] = sj;
            mnew = fmaxf(mnew, sj);
        }

        // rescale previous state
        float corr = __expf(m - mnew);
        m = mnew;
        l *= corr;
#pragma unroll
        for (int c = 0; c < D; c++) o[c] *= corr;

        // pass 2: softmax weights + PV accumulation
#pragma unroll 2
        for (int j = 0; j < BN; j++) {
            float p = __expf(srow_sh[j] - m);
            l += p;
            const float* vrow = &Vsh[j * D];
#pragma unroll
            for (int c = 0; c < D; c += 4) {
                float4 vv = *(const float4*)&vrow[c];
                o[c+0] = fmaf(p, vv.x, o[c+0]);
                o[c+1] = fmaf(p, vv.y, o[c+1]);
                o[c+2] = fmaf(p, vv.z, o[c+2]);
                o[c+3] = fmaf(p, vv.w, o[c+3]);
            }
        }
    }

    const float inv = 1.0f / l;
    float* orow = g_attn + ((size_t)(b * S + r)) * E + h * D;
#pragma unroll
    for (int c = 0; c < D; c += 4) {
        float4 t;
        t.x = o[c+0] * inv;
        t.y = o[c+1] * inv;
        t.z = o[c+2] * inv;
        t.w = o[c+3] * inv;
        *(float4*)&orow[c] = t;
    }
}

// ---------------------------------------------------------------------------
// Output projection: C[M=BS, E] = attn @ W^T + bias.
// 64x64 block tile, 256 threads, 4x4 micro-tile, k-major smem tiles so
// fragments are single LDS.128 loads.
// ---------------------------------------------------------------------------
#define PBK 16

__global__ void __launch_bounds__(256)
proj_kernel(const float* __restrict__ W,
            const float* __restrict__ bias,
            float* __restrict__ C)
{
    __shared__ float As[PBK][68];   // [k][m], padded
    __shared__ float Ws[PBK][68];   // [k][n], padded

    const int tid = threadIdx.x;
    const int tx  = tid & 15;       // 0..15 -> n micro
    const int ty  = tid >> 4;       // 0..15 -> m micro
    const int m0  = blockIdx.x * 64;
    const int n0  = blockIdx.y * 64;

    const int lrow = tid >> 2;          // 0..63
    const int lc4  = (tid & 3) << 2;    // 0,4,8,12

    const float* A = g_attn;

    float acc[4][4];
#pragma unroll
    for (int i = 0; i < 4; i++)
#pragma unroll
        for (int j = 0; j < 4; j++) acc[i][j] = 0.0f;

    for (int k0 = 0; k0 < E; k0 += PBK) {
        float4 av = *(const float4*)&A[(size_t)(m0 + lrow) * E + k0 + lc4];
        float4 wv = *(const float4*)&W[(size_t)(n0 + lrow) * E + k0 + lc4];
        __syncthreads();
        As[lc4+0][lrow] = av.x;  As[lc4+1][lrow] = av.y;
        As[lc4+2][lrow] = av.z;  As[lc4+3][lrow] = av.w;
        Ws[lc4+0][lrow] = wv.x;  Ws[lc4+1][lrow] = wv.y;
        Ws[lc4+2][lrow] = wv.z;  Ws[lc4+3][lrow] = wv.w;
        __syncthreads();

#pragma unroll
        for (int kk = 0; kk < PBK; kk++) {
            float4 af = *(const float4*)&As[kk][ty * 4];
            float4 wf = *(const float4*)&Ws[kk][tx * 4];
            float a[4] = {af.x, af.y, af.z, af.w};
            float w[4] = {wf.x, wf.y, wf.z, wf.w};
#pragma unroll
            for (int i = 0; i < 4; i++)
#pragma unroll
                for (int j = 0; j < 4; j++)
                    acc[i][j] = fmaf(a[i], w[j], acc[i][j]);
        }
    }

    float4 bv = *(const float4*)&bias[n0 + tx * 4];
#pragma unroll
    for (int i = 0; i < 4; i++) {
        float4 t;
        t.x = acc[i][0] + bv.x;
        t.y = acc[i][1] + bv.y;
        t.z = acc[i][2] + bv.z;
        t.w = acc[i][3] + bv.w;
        *(float4*)&C[(size_t)(m0 + ty * 4 + i) * E + n0 + tx * 4] = t;
    }
}

// ---------------------------------------------------------------------------
extern "C" void kernel_launch(void* const* d_in, const int* in_sizes, int n_in,
                              void* d_out, int out_size)
{
    const float* q     = (const float*)d_in[0];
    const float* k     = (const float*)d_in[1];
    const float* v     = (const float*)d_in[2];
    const float* w_out = (const float*)d_in[3];
    const float* b_out = (const float*)d_in[4];
    float* out = (float*)d_out;

    const int smem_bytes = (2 * BN * D + BM * 65) * (int)sizeof(float); // 66048
    cudaFuncSetAttribute(attn_kernel,
                         cudaFuncAttributeMaxDynamicSharedMemorySize, smem_bytes);

    dim3 g1(S / BM, H, B);
    attn_kernel<<<g1, BM, smem_bytes>>>(q, k, v);

    dim3 g2((B * S) / 64, E / 64);
    proj_kernel<<<g2, 256>>>(w_out, b_out, out);
}

// round 2
// speedup vs baseline: 3.0035x; 3.0035x over previous
#include <cuda_runtime.h>
#include <stdint.h>

#define B 4
#define S 2048
#define E 1024
#define H 16
#define D 64

#define KS 68   // K smem row stride (floats)
#define VS 72   // V smem row stride
#define PS 68   // P smem row stride

// scratch for attention output [B, S, E]
__device__ float g_attn[(size_t)B * S * E];

__device__ __forceinline__ uint32_t f2tf(float f) {
    uint32_t u;
    asm("cvt.rna.tf32.f32 %0, %1;" : "=r"(u) : "f"(f));
    return u;
}

__device__ __forceinline__ void mma_tf32(float c[4], const uint32_t a[4], const uint32_t b[2]) {
    asm volatile(
        "mma.sync.aligned.m16n8k8.row.col.f32.tf32.tf32.f32 "
        "{%0,%1,%2,%3}, {%4,%5,%6,%7}, {%8,%9}, {%0,%1,%2,%3};"
        : "+f"(c[0]), "+f"(c[1]), "+f"(c[2]), "+f"(c[3])
        : "r"(a[0]), "r"(a[1]), "r"(a[2]), "r"(a[3]), "r"(b[0]), "r"(b[1]));
}

// ---------------------------------------------------------------------------
// Flash attention with tf32 mma.sync. 4 warps x 16 q-rows = 64 q rows/block.
// ---------------------------------------------------------------------------
__global__ void __launch_bounds__(128)
attn_mma_kernel(const float* __restrict__ q,
                const float* __restrict__ k,
                const float* __restrict__ v)
{
    extern __shared__ float smf[];
    float* Ksh = smf;                 // [64][KS]
    float* Vsh = Ksh + 64 * KS;       // [64][VS]
    float* Psh = Vsh + 64 * VS;       // [64][PS] (warp w owns rows w*16..w*16+15)

    const int tid  = threadIdx.x;
    const int warp = tid >> 5;
    const int lane = tid & 31;
    const int grp  = lane >> 2;   // 0..7
    const int qid  = lane & 3;    // 0..3

    const int h = blockIdx.y, b = blockIdx.z;
    const int qbase = blockIdx.x * 64 + warp * 16;

    // ---- Q as A-fragments (pre-scaled, tf32) : qa[kstep][4] ----
    uint32_t qa[8][4];
    {
        const float scale = 0.125f;   // 1/sqrt(64)
        const float* qb = q + ((size_t)(b * S + qbase)) * E + h * D;
#pragma unroll
        for (int kk = 0; kk < 8; kk++) {
            int c0 = kk * 8 + qid, c1 = c0 + 4;
            qa[kk][0] = f2tf(qb[(size_t)grp       * E + c0] * scale);
            qa[kk][1] = f2tf(qb[(size_t)(grp + 8) * E + c0] * scale);
            qa[kk][2] = f2tf(qb[(size_t)grp       * E + c1] * scale);
            qa[kk][3] = f2tf(qb[(size_t)(grp + 8) * E + c1] * scale);
        }
    }

    float o[8][4];
#pragma unroll
    for (int t = 0; t < 8; t++) { o[t][0] = o[t][1] = o[t][2] = o[t][3] = 0.f; }
    float m0 = -1e30f, m1 = -1e30f;
    float l0 = 0.f,    l1 = 0.f;

    const float* kb = k + ((size_t)(b * S)) * E + h * D;
    const float* vb = v + ((size_t)(b * S)) * E + h * D;
    float* Pw = Psh + warp * 16 * PS;

    for (int kt = 0; kt < S / 64; kt++) {
        __syncthreads();
        // ---- cooperative load + tf32 convert of K/V tiles (64x64) ----
#pragma unroll
        for (int i = 0; i < 8; i++) {
            int f = i * 128 + tid;
            int j = f >> 4;               // 0..63 tile row
            int c = (f & 15) << 2;        // 0,4,..,60
            float4 k4 = *(const float4*)&kb[(size_t)(kt * 64 + j) * E + c];
            float4 v4 = *(const float4*)&vb[(size_t)(kt * 64 + j) * E + c];
            *(uint4*)&Ksh[j * KS + c] =
                make_uint4(f2tf(k4.x), f2tf(k4.y), f2tf(k4.z), f2tf(k4.w));
            *(uint4*)&Vsh[j * VS + c] =
                make_uint4(f2tf(v4.x), f2tf(v4.y), f2tf(v4.z), f2tf(v4.w));
        }
        __syncthreads();

        // ---- scores S = Q K^T : 8 ntiles x 8 ksteps ----
        float sc[8][4];
#pragma unroll
        for (int t = 0; t < 8; t++) { sc[t][0] = sc[t][1] = sc[t][2] = sc[t][3] = 0.f; }
        const uint32_t* kp = (const uint32_t*)Ksh;
#pragma unroll
        for (int kk = 0; kk < 8; kk++) {
#pragma unroll
            for (int t = 0; t < 8; t++) {
                uint32_t bb[2];
                bb[0] = kp[(t * 8 + grp) * KS + kk * 8 + qid];
                bb[1] = kp[(t * 8 + grp) * KS + kk * 8 + qid + 4];
                mma_tf32(sc[t], qa[kk], bb);
            }
        }

        // ---- online softmax ----
        float r0 = -1e30f, r1 = -1e30f;
#pragma unroll
        for (int t = 0; t < 8; t++) {
            r0 = fmaxf(r0, fmaxf(sc[t][0], sc[t][1]));
            r1 = fmaxf(r1, fmaxf(sc[t][2], sc[t][3]));
        }
        r0 = fmaxf(r0, __shfl_xor_sync(0xffffffffu, r0, 1));
        r0 = fmaxf(r0, __shfl_xor_sync(0xffffffffu, r0, 2));
        r1 = fmaxf(r1, __shfl_xor_sync(0xffffffffu, r1, 1));
        r1 = fmaxf(r1, __shfl_xor_sync(0xffffffffu, r1, 2));

        float mn0 = fmaxf(m0, r0), mn1 = fmaxf(m1, r1);
        float corr0 = __expf(m0 - mn0), corr1 = __expf(m1 - mn1);
        m0 = mn0; m1 = mn1;
        l0 *= corr0; l1 *= corr1;
#pragma unroll
        for (int t = 0; t < 8; t++) {
            o[t][0] *= corr0; o[t][1] *= corr0;
            o[t][2] *= corr1; o[t][3] *= corr1;
        }

        uint32_t* pp = (uint32_t*)Pw;
#pragma unroll
        for (int t = 0; t < 8; t++) {
            float p0 = __expf(sc[t][0] - mn0);
            float p1 = __expf(sc[t][1] - mn0);
            float p2 = __expf(sc[t][2] - mn1);
            float p3 = __expf(sc[t][3] - mn1);
            l0 += p0 + p1;
            l1 += p2 + p3;
            int col = t * 8 + 2 * qid;
            *(uint2*)&pp[grp       * PS + col] = make_uint2(f2tf(p0), f2tf(p1));
            *(uint2*)&pp[(grp + 8) * PS + col] = make_uint2(f2tf(p2), f2tf(p3));
        }
        __syncwarp();

        // ---- O += P V : 8 ksteps x 8 ntiles ----
        const uint32_t* vp = (const uint32_t*)Vsh;
#pragma unroll
        for (int kk = 0; kk < 8; kk++) {
            uint32_t pa[4];
            pa[0] = pp[grp       * PS + kk * 8 + qid];
            pa[1] = pp[(grp + 8) * PS + kk * 8 + qid];
            pa[2] = pp[grp       * PS + kk * 8 + qid + 4];
            pa[3] = pp[(grp + 8) * PS + kk * 8 + qid + 4];
#pragma unroll
            for (int t = 0; t < 8; t++) {
                uint32_t bb[2];
                bb[0] = vp[(kk * 8 + qid)     * VS + t * 8 + grp];
                bb[1] = vp[(kk * 8 + qid + 4) * VS + t * 8 + grp];
                mma_tf32(o[t], pa, bb);
            }
        }
    }

    // ---- epilogue ----
    l0 += __shfl_xor_sync(0xffffffffu, l0, 1);
    l0 += __shfl_xor_sync(0xffffffffu, l0, 2);
    l1 += __shfl_xor_sync(0xffffffffu, l1, 1);
    l1 += __shfl_xor_sync(0xffffffffu, l1, 2);
    float inv0 = 1.0f / l0, inv1 = 1.0f / l1;

    float* ob = g_attn + ((size_t)(b * S + qbase)) * E + h * D;
#pragma unroll
    for (int t = 0; t < 8; t++) {
        int col = t * 8 + 2 * qid;
        float2 w0 = make_float2(o[t][0] * inv0, o[t][1] * inv0);
        float2 w1 = make_float2(o[t][2] * inv1, o[t][3] * inv1);
        *(float2*)&ob[(size_t)grp       * E + col] = w0;
        *(float2*)&ob[(size_t)(grp + 8) * E + col] = w1;
    }
}

// ---------------------------------------------------------------------------
// Output projection: C[M=BS, E] = attn @ W^T + bias. (unchanged, known-good)
// ---------------------------------------------------------------------------
#define PBK 16

__global__ void __launch_bounds__(256)
proj_kernel(const float* __restrict__ W,
            const float* __restrict__ bias,
            float* __restrict__ C)
{
    __shared__ float As[PBK][68];
    __shared__ float Ws[PBK][68];

    const int tid = threadIdx.x;
    const int tx  = tid & 15;
    const int ty  = tid >> 4;
    const int m0  = blockIdx.x * 64;
    const int n0  = blockIdx.y * 64;

    const int lrow = tid >> 2;
    const int lc4  = (tid & 3) << 2;

    const float* A = g_attn;

    float acc[4][4];
#pragma unroll
    for (int i = 0; i < 4; i++)
#pragma unroll
        for (int j = 0; j < 4; j++) acc[i][j] = 0.0f;

    for (int k0 = 0; k0 < E; k0 += PBK) {
        float4 av = *(const float4*)&A[(size_t)(m0 + lrow) * E + k0 + lc4];
        float4 wv = *(const float4*)&W[(size_t)(n0 + lrow) * E + k0 + lc4];
        __syncthreads();
        As[lc4+0][lrow] = av.x;  As[lc4+1][lrow] = av.y;
        As[lc4+2][lrow] = av.z;  As[lc4+3][lrow] = av.w;
        Ws[lc4+0][lrow] = wv.x;  Ws[lc4+1][lrow] = wv.y;
        Ws[lc4+2][lrow] = wv.z;  Ws[lc4+3][lrow] = wv.w;
        __syncthreads();

#pragma unroll
        for (int kk = 0; kk < PBK; kk++) {
            float4 af = *(const float4*)&As[kk][ty * 4];
            float4 wf = *(const float4*)&Ws[kk][tx * 4];
            float a[4] = {af.x, af.y, af.z, af.w};
            float w[4] = {wf.x, wf.y, wf.z, wf.w};
#pragma unroll
            for (int i = 0; i < 4; i++)
#pragma unroll
                for (int j = 0; j < 4; j++)
                    acc[i][j] = fmaf(a[i], w[j], acc[i][j]);
        }
    }

    float4 bv = *(const float4*)&bias[n0 + tx * 4];
#pragma unroll
    for (int i = 0; i < 4; i++) {
        float4 t;
        t.x = acc[i][0] + bv.x;
        t.y = acc[i][1] + bv.y;
        t.z = acc[i][2] + bv.z;
        t.w = acc[i][3] + bv.w;
        *(float4*)&C[(size_t)(m0 + ty * 4 + i) * E + n0 + tx * 4] = t;
    }
}

// ---------------------------------------------------------------------------
extern "C" void kernel_launch(void* const* d_in, const int* in_sizes, int n_in,
                              void* d_out, int out_size)
{
    const float* q     = (const float*)d_in[0];
    const float* k     = (const float*)d_in[1];
    const float* v     = (const float*)d_in[2];
    const float* w_out = (const float*)d_in[3];
    const float* b_out = (const float*)d_in[4];
    float* out = (float*)d_out;

    const int smem_bytes = (64 * KS + 64 * VS + 64 * PS) * (int)sizeof(float); // 53248
    cudaFuncSetAttribute(attn_mma_kernel,
                         cudaFuncAttributeMaxDynamicSharedMemorySize, smem_bytes);

    dim3 g1(S / 64, H, B);
    attn_mma_kernel<<<g1, 128, smem_bytes>>>(q, k, v);

    dim3 g2((B * S) / 64, E / 64);
    proj_kernel<<<g2, 256>>>(w_out, b_out, out);
}

// round 3
// speedup vs baseline: 4.4209x; 1.4719x over previous
#include <cuda_runtime.h>
#include <stdint.h>

#define B 4
#define S 2048
#define E 1024
#define H 16
#define D 64

#define KS 68   // K smem row stride (floats)
#define VS 72   // V smem row stride
#define PS 68   // P smem row stride

// scratch for attention output [B, S, E]
__device__ float g_attn[(size_t)B * S * E];

__device__ __forceinline__ uint32_t f2tf(float f) {
    uint32_t u;
    asm("cvt.rna.tf32.f32 %0, %1;" : "=r"(u) : "f"(f));
    return u;
}

__device__ __forceinline__ void mma_tf32(float c[4], const uint32_t a[4], const uint32_t b[2]) {
    asm volatile(
        "mma.sync.aligned.m16n8k8.row.col.f32.tf32.tf32.f32 "
        "{%0,%1,%2,%3}, {%4,%5,%6,%7}, {%8,%9}, {%0,%1,%2,%3};"
        : "+f"(c[0]), "+f"(c[1]), "+f"(c[2]), "+f"(c[3])
        : "r"(a[0]), "r"(a[1]), "r"(a[2]), "r"(a[3]), "r"(b[0]), "r"(b[1]));
}

// ---------------------------------------------------------------------------
// Flash attention with tf32 mma.sync. 4 warps x 16 q-rows = 64 q rows/block.
// (unchanged from R2 — known good)
// ---------------------------------------------------------------------------
__global__ void __launch_bounds__(128)
attn_mma_kernel(const float* __restrict__ q,
                const float* __restrict__ k,
                const float* __restrict__ v)
{
    extern __shared__ float smf[];
    float* Ksh = smf;                 // [64][KS]
    float* Vsh = Ksh + 64 * KS;       // [64][VS]
    float* Psh = Vsh + 64 * VS;       // [64][PS]

    const int tid  = threadIdx.x;
    const int warp = tid >> 5;
    const int lane = tid & 31;
    const int grp  = lane >> 2;
    const int qid  = lane & 3;

    const int h = blockIdx.y, b = blockIdx.z;
    const int qbase = blockIdx.x * 64 + warp * 16;

    uint32_t qa[8][4];
    {
        const float scale = 0.125f;
        const float* qb = q + ((size_t)(b * S + qbase)) * E + h * D;
#pragma unroll
        for (int kk = 0; kk < 8; kk++) {
            int c0 = kk * 8 + qid, c1 = c0 + 4;
            qa[kk][0] = f2tf(qb[(size_t)grp       * E + c0] * scale);
            qa[kk][1] = f2tf(qb[(size_t)(grp + 8) * E + c0] * scale);
            qa[kk][2] = f2tf(qb[(size_t)grp       * E + c1] * scale);
            qa[kk][3] = f2tf(qb[(size_t)(grp + 8) * E + c1] * scale);
        }
    }

    float o[8][4];
#pragma unroll
    for (int t = 0; t < 8; t++) { o[t][0] = o[t][1] = o[t][2] = o[t][3] = 0.f; }
    float m0 = -1e30f, m1 = -1e30f;
    float l0 = 0.f,    l1 = 0.f;

    const float* kb = k + ((size_t)(b * S)) * E + h * D;
    const float* vb = v + ((size_t)(b * S)) * E + h * D;
    float* Pw = Psh + warp * 16 * PS;

    for (int kt = 0; kt < S / 64; kt++) {
        __syncthreads();
#pragma unroll
        for (int i = 0; i < 8; i++) {
            int f = i * 128 + tid;
            int j = f >> 4;
            int c = (f & 15) << 2;
            float4 k4 = *(const float4*)&kb[(size_t)(kt * 64 + j) * E + c];
            float4 v4 = *(const float4*)&vb[(size_t)(kt * 64 + j) * E + c];
            *(uint4*)&Ksh[j * KS + c] =
                make_uint4(f2tf(k4.x), f2tf(k4.y), f2tf(k4.z), f2tf(k4.w));
            *(uint4*)&Vsh[j * VS + c] =
                make_uint4(f2tf(v4.x), f2tf(v4.y), f2tf(v4.z), f2tf(v4.w));
        }
        __syncthreads();

        float sc[8][4];
#pragma unroll
        for (int t = 0; t < 8; t++) { sc[t][0] = sc[t][1] = sc[t][2] = sc[t][3] = 0.f; }
        const uint32_t* kp = (const uint32_t*)Ksh;
#pragma unroll
        for (int kk = 0; kk < 8; kk++) {
#pragma unroll
            for (int t = 0; t < 8; t++) {
                uint32_t bb[2];
                bb[0] = kp[(t * 8 + grp) * KS + kk * 8 + qid];
                bb[1] = kp[(t * 8 + grp) * KS + kk * 8 + qid + 4];
                mma_tf32(sc[t], qa[kk], bb);
            }
        }

        float r0 = -1e30f, r1 = -1e30f;
#pragma unroll
        for (int t = 0; t < 8; t++) {
            r0 = fmaxf(r0, fmaxf(sc[t][0], sc[t][1]));
            r1 = fmaxf(r1, fmaxf(sc[t][2], sc[t][3]));
        }
        r0 = fmaxf(r0, __shfl_xor_sync(0xffffffffu, r0, 1));
        r0 = fmaxf(r0, __shfl_xor_sync(0xffffffffu, r0, 2));
        r1 = fmaxf(r1, __shfl_xor_sync(0xffffffffu, r1, 1));
        r1 = fmaxf(r1, __shfl_xor_sync(0xffffffffu, r1, 2));

        float mn0 = fmaxf(m0, r0), mn1 = fmaxf(m1, r1);
        float corr0 = __expf(m0 - mn0), corr1 = __expf(m1 - mn1);
        m0 = mn0; m1 = mn1;
        l0 *= corr0; l1 *= corr1;
#pragma unroll
        for (int t = 0; t < 8; t++) {
            o[t][0] *= corr0; o[t][1] *= corr0;
            o[t][2] *= corr1; o[t][3] *= corr1;
        }

        uint32_t* pp = (uint32_t*)Pw;
#pragma unroll
        for (int t = 0; t < 8; t++) {
            float p0 = __expf(sc[t][0] - mn0);
            float p1 = __expf(sc[t][1] - mn0);
            float p2 = __expf(sc[t][2] - mn1);
            float p3 = __expf(sc[t][3] - mn1);
            l0 += p0 + p1;
            l1 += p2 + p3;
            int col = t * 8 + 2 * qid;
            *(uint2*)&pp[grp       * PS + col] = make_uint2(f2tf(p0), f2tf(p1));
            *(uint2*)&pp[(grp + 8) * PS + col] = make_uint2(f2tf(p2), f2tf(p3));
        }
        __syncwarp();

        const uint32_t* vp = (const uint32_t*)Vsh;
#pragma unroll
        for (int kk = 0; kk < 8; kk++) {
            uint32_t pa[4];
            pa[0] = pp[grp       * PS + kk * 8 + qid];
            pa[1] = pp[(grp + 8) * PS + kk * 8 + qid];
            pa[2] = pp[grp       * PS + kk * 8 + qid + 4];
            pa[3] = pp[(grp + 8) * PS + kk * 8 + qid + 4];
#pragma unroll
            for (int t = 0; t < 8; t++) {
                uint32_t bb[2];
                bb[0] = vp[(kk * 8 + qid)     * VS + t * 8 + grp];
                bb[1] = vp[(kk * 8 + qid + 4) * VS + t * 8 + grp];
                mma_tf32(o[t], pa, bb);
            }
        }
    }

    l0 += __shfl_xor_sync(0xffffffffu, l0, 1);
    l0 += __shfl_xor_sync(0xffffffffu, l0, 2);
    l1 += __shfl_xor_sync(0xffffffffu, l1, 1);
    l1 += __shfl_xor_sync(0xffffffffu, l1, 2);
    float inv0 = 1.0f / l0, inv1 = 1.0f / l1;

    float* ob = g_attn + ((size_t)(b * S + qbase)) * E + h * D;
#pragma unroll
    for (int t = 0; t < 8; t++) {
        int col = t * 8 + 2 * qid;
        float2 w0 = make_float2(o[t][0] * inv0, o[t][1] * inv0);
        float2 w1 = make_float2(o[t][2] * inv1, o[t][3] * inv1);
        *(float2*)&ob[(size_t)grp       * E + col] = w0;
        *(float2*)&ob[(size_t)(grp + 8) * E + col] = w1;
    }
}

// ---------------------------------------------------------------------------
// Output projection with tf32 mma.sync: C[8192,1024] = g_attn @ W^T + bias.
// 128x128 block tile, 256 threads / 8 warps, each warp 16 rows x 128 cols.
// K-chunk 64. W's B-fragment layout identical to K's in attention.
// ---------------------------------------------------------------------------
#define PROJ_LDS 68
#define PBKC 64

__global__ void __launch_bounds__(256, 2)
proj_mma_kernel(const float* __restrict__ W,
                const float* __restrict__ bias,
                float* __restrict__ C)
{
    extern __shared__ float smf[];
    float* As = smf;                    // [128][68] tf32 bits
    float* Ws = smf + 128 * PROJ_LDS;   // [128][68] tf32 bits

    const int tid  = threadIdx.x;
    const int warp = tid >> 5;
    const int lane = tid & 31;
    const int grp  = lane >> 2;
    const int qid  = lane & 3;

    const int m0 = blockIdx.x * 128;
    const int n0 = blockIdx.y * 128;
    const int mrow = warp * 16;           // warp's 16-row slice

    const float* A = g_attn;

    float acc[16][4];
#pragma unroll
    for (int t = 0; t < 16; t++) { acc[t][0] = acc[t][1] = acc[t][2] = acc[t][3] = 0.f; }

    // load indices for cooperative tile fill: 128 rows x 64 cols = 2048 float4
    const int lrow = tid >> 4;            // 0..15 base row (x8 iters -> 128)
    const int lc4  = (tid & 15) << 2;     // col 0,4,..,60

    for (int k0 = 0; k0 < E; k0 += PBKC) {
        __syncthreads();
#pragma unroll
        for (int i = 0; i < 8; i++) {
            int row = i * 16 + lrow;
            float4 a4 = *(const float4*)&A[(size_t)(m0 + row) * E + k0 + lc4];
            float4 w4 = *(const float4*)&W[(size_t)(n0 + row) * E + k0 + lc4];
            *(uint4*)&As[row * PROJ_LDS + lc4] =
                make_uint4(f2tf(a4.x), f2tf(a4.y), f2tf(a4.z), f2tf(a4.w));
            *(uint4*)&Ws[row * PROJ_LDS + lc4] =
                make_uint4(f2tf(w4.x), f2tf(w4.y), f2tf(w4.z), f2tf(w4.w));
        }
        __syncthreads();

        const uint32_t* ap = (const uint32_t*)As;
        const uint32_t* wp = (const uint32_t*)Ws;
#pragma unroll
        for (int kk = 0; kk < 8; kk++) {
            uint32_t a[4];
            a[0] = ap[(mrow + grp)     * PROJ_LDS + kk * 8 + qid];
            a[1] = ap[(mrow + grp + 8) * PROJ_LDS + kk * 8 + qid];
            a[2] = ap[(mrow + grp)     * PROJ_LDS + kk * 8 + qid + 4];
            a[3] = ap[(mrow + grp + 8) * PROJ_LDS + kk * 8 + qid + 4];
#pragma unroll
            for (int t = 0; t < 16; t++) {
                uint32_t bb[2];
                bb[0] = wp[(t * 8 + grp) * PROJ_LDS + kk * 8 + qid];
                bb[1] = wp[(t * 8 + grp) * PROJ_LDS + kk * 8 + qid + 4];
                mma_tf32(acc[t], a, bb);
            }
        }
    }

    // epilogue: bias + store. Thread owns rows (m0+mrow+grp, +8),
    // cols n0 + t*8 + 2*qid, +1 for t in 0..15.
#pragma unroll
    for (int t = 0; t < 16; t++) {
        int col = n0 + t * 8 + 2 * qid;
        float b0 = bias[col], b1 = bias[col + 1];
        float2 w0 = make_float2(acc[t][0] + b0, acc[t][1] + b1);
        float2 w1 = make_float2(acc[t][2] + b0, acc[t][3] + b1);
        *(float2*)&C[(size_t)(m0 + mrow + grp)     * E + col] = w0;
        *(float2*)&C[(size_t)(m0 + mrow + grp + 8) * E + col] = w1;
    }
}

// ---------------------------------------------------------------------------
extern "C" void kernel_launch(void* const* d_in, const int* in_sizes, int n_in,
                              void* d_out, int out_size)
{
    const float* q     = (const float*)d_in[0];
    const float* k     = (const float*)d_in[1];
    const float* v     = (const float*)d_in[2];
    const float* w_out = (const float*)d_in[3];
    const float* b_out = (const float*)d_in[4];
    float* out = (float*)d_out;

    const int attn_smem = (64 * KS + 64 * VS + 64 * PS) * (int)sizeof(float); // 53248
    cudaFuncSetAttribute(attn_mma_kernel,
                         cudaFuncAttributeMaxDynamicSharedMemorySize, attn_smem);

    dim3 g1(S / 64, H, B);
    attn_mma_kernel<<<g1, 128, attn_smem>>>(q, k, v);

    const int proj_smem = 2 * 128 * PROJ_LDS * (int)sizeof(float); // 69632
    cudaFuncSetAttribute(proj_mma_kernel,
                         cudaFuncAttributeMaxDynamicSharedMemorySize, proj_smem);

    dim3 g2((B * S) / 128, E / 128);
    proj_mma_kernel<<<g2, 256, proj_smem>>>(w_out, b_out, out);
}

// round 4
// speedup vs baseline: 4.7521x; 1.0749x over previous
#include <cuda_runtime.h>
#include <stdint.h>

#define B 4
#define S 2048
#define E 1024
#define H 16
#define D 64

#define BN 32   // k rows per tile (attention)
#define KS 68   // K smem row stride (floats)
#define VS 72   // V smem row stride
#define PS 36   // P smem row stride (32 cols + 4 pad)

// scratch for attention output [B, S, E]
__device__ float g_attn[(size_t)B * S * E];

__device__ __forceinline__ uint32_t f2tf(float f) {
    uint32_t u;
    asm("cvt.rna.tf32.f32 %0, %1;" : "=r"(u) : "f"(f));
    return u;
}

__device__ __forceinline__ void mma_tf32(float c[4], const uint32_t a[4], const uint32_t b[2]) {
    asm volatile(
        "mma.sync.aligned.m16n8k8.row.col.f32.tf32.tf32.f32 "
        "{%0,%1,%2,%3}, {%4,%5,%6,%7}, {%8,%9}, {%0,%1,%2,%3};"
        : "+f"(c[0]), "+f"(c[1]), "+f"(c[2]), "+f"(c[3])
        : "r"(a[0]), "r"(a[1]), "r"(a[2]), "r"(a[3]), "r"(b[0]), "r"(b[1]));
}

// ---------------------------------------------------------------------------
// Flash attention, tf32 mma.sync. 4 warps x 32 q-rows = 128 q rows/block.
// Each warp owns two 16-row A-tiles so every B-fragment load feeds 2 mmas.
// K-tile BN=32 keeps the transient score registers at 32.
// ---------------------------------------------------------------------------
__global__ void __launch_bounds__(128)
attn_mma_kernel(const float* __restrict__ q,
                const float* __restrict__ k,
                const float* __restrict__ v)
{
    extern __shared__ float smf[];
    float* Ksh = smf;                      // [32][KS]
    float* Vsh = smf + BN * KS;            // [32][VS]
    float* Psh = smf + BN * KS + BN * VS;  // [128][PS]

    const int tid  = threadIdx.x;
    const int warp = tid >> 5;
    const int lane = tid & 31;
    const int grp  = lane >> 2;   // 0..7
    const int qid  = lane & 3;    // 0..3

    const int h = blockIdx.y, b = blockIdx.z;
    const int qbase = blockIdx.x * 128 + warp * 32;

    // ---- Q as A-fragments for two 16-row tiles (pre-scaled, tf32) ----
    uint32_t qa[2][8][4];
    {
        const float scale = 0.125f;   // 1/sqrt(64)
        const float* qb = q + ((size_t)(b * S + qbase)) * E + h * D;
#pragma unroll
        for (int a = 0; a < 2; a++) {
            int r0 = a * 16 + grp;
#pragma unroll
            for (int kk = 0; kk < 8; kk++) {
                int c0 = kk * 8 + qid, c1 = c0 + 4;
                qa[a][kk][0] = f2tf(qb[(size_t)r0       * E + c0] * scale);
                qa[a][kk][1] = f2tf(qb[(size_t)(r0 + 8) * E + c0] * scale);
                qa[a][kk][2] = f2tf(qb[(size_t)r0       * E + c1] * scale);
                qa[a][kk][3] = f2tf(qb[(size_t)(r0 + 8) * E + c1] * scale);
            }
        }
    }

    float o[2][8][4];
#pragma unroll
    for (int a = 0; a < 2; a++)
#pragma unroll
        for (int t = 0; t < 8; t++) { o[a][t][0] = o[a][t][1] = o[a][t][2] = o[a][t][3] = 0.f; }
    float m0[2] = {-1e30f, -1e30f}, m1[2] = {-1e30f, -1e30f};
    float l0[2] = {0.f, 0.f},       l1[2] = {0.f, 0.f};

    const float* kb = k + ((size_t)(b * S)) * E + h * D;
    const float* vb = v + ((size_t)(b * S)) * E + h * D;
    float* Pw = Psh + warp * 32 * PS;

    for (int kt = 0; kt < S / BN; kt++) {
        __syncthreads();
        // ---- cooperative load + tf32 convert of K/V tiles (32x64) ----
#pragma unroll
        for (int i = 0; i < 4; i++) {
            int f = i * 128 + tid;
            int j = f >> 4;               // 0..31
            int c = (f & 15) << 2;        // 0,4,..,60
            float4 k4 = *(const float4*)&kb[(size_t)(kt * BN + j) * E + c];
            float4 v4 = *(const float4*)&vb[(size_t)(kt * BN + j) * E + c];
            *(uint4*)&Ksh[j * KS + c] =
                make_uint4(f2tf(k4.x), f2tf(k4.y), f2tf(k4.z), f2tf(k4.w));
            *(uint4*)&Vsh[j * VS + c] =
                make_uint4(f2tf(v4.x), f2tf(v4.y), f2tf(v4.z), f2tf(v4.w));
        }
        __syncthreads();

        // ---- scores: 2 A-tiles x 4 ntiles, B shared across A-tiles ----
        float sc[2][4][4];
#pragma unroll
        for (int a = 0; a < 2; a++)
#pragma unroll
            for (int t = 0; t < 4; t++) { sc[a][t][0] = sc[a][t][1] = sc[a][t][2] = sc[a][t][3] = 0.f; }
        const uint32_t* kp = (const uint32_t*)Ksh;
#pragma unroll
        for (int kk = 0; kk < 8; kk++) {
#pragma unroll
            for (int t = 0; t < 4; t++) {
                uint32_t bb[2];
                bb[0] = kp[(t * 8 + grp) * KS + kk * 8 + qid];
                bb[1] = kp[(t * 8 + grp) * KS + kk * 8 + qid + 4];
                mma_tf32(sc[0][t], qa[0][kk], bb);
                mma_tf32(sc[1][t], qa[1][kk], bb);
            }
        }

        // ---- online softmax per A-tile ----
        uint32_t* pp = (uint32_t*)Pw;
#pragma unroll
        for (int a = 0; a < 2; a++) {
            float r0 = -1e30f, r1 = -1e30f;
#pragma unroll
            for (int t = 0; t < 4; t++) {
                r0 = fmaxf(r0, fmaxf(sc[a][t][0], sc[a][t][1]));
                r1 = fmaxf(r1, fmaxf(sc[a][t][2], sc[a][t][3]));
            }
            r0 = fmaxf(r0, __shfl_xor_sync(0xffffffffu, r0, 1));
            r0 = fmaxf(r0, __shfl_xor_sync(0xffffffffu, r0, 2));
            r1 = fmaxf(r1, __shfl_xor_sync(0xffffffffu, r1, 1));
            r1 = fmaxf(r1, __shfl_xor_sync(0xffffffffu, r1, 2));

            float mn0 = fmaxf(m0[a], r0), mn1 = fmaxf(m1[a], r1);
            float corr0 = __expf(m0[a] - mn0), corr1 = __expf(m1[a] - mn1);
            m0[a] = mn0; m1[a] = mn1;
            l0[a] *= corr0; l1[a] *= corr1;
#pragma unroll
            for (int t = 0; t < 8; t++) {
                o[a][t][0] *= corr0; o[a][t][1] *= corr0;
                o[a][t][2] *= corr1; o[a][t][3] *= corr1;
            }

            int pr = a * 16 + grp;
#pragma unroll
            for (int t = 0; t < 4; t++) {
                float p0 = __expf(sc[a][t][0] - mn0);
                float p1 = __expf(sc[a][t][1] - mn0);
                float p2 = __expf(sc[a][t][2] - mn1);
                float p3 = __expf(sc[a][t][3] - mn1);
                l0[a] += p0 + p1;
                l1[a] += p2 + p3;
                int col = t * 8 + 2 * qid;
                *(uint2*)&pp[pr       * PS + col] = make_uint2(f2tf(p0), f2tf(p1));
                *(uint2*)&pp[(pr + 8) * PS + col] = make_uint2(f2tf(p2), f2tf(p3));
            }
        }
        __syncwarp();

        // ---- O += P V : V B-fragments shared across the two A-tiles ----
        const uint32_t* vp = (const uint32_t*)Vsh;
#pragma unroll
        for (int kk = 0; kk < 4; kk++) {
            uint32_t pa[2][4];
#pragma unroll
            for (int a = 0; a < 2; a++) {
                int pr = a * 16 + grp;
                pa[a][0] = pp[pr       * PS + kk * 8 + qid];
                pa[a][1] = pp[(pr + 8) * PS + kk * 8 + qid];
                pa[a][2] = pp[pr       * PS + kk * 8 + qid + 4];
                pa[a][3] = pp[(pr + 8) * PS + kk * 8 + qid + 4];
            }
#pragma unroll
            for (int t = 0; t < 8; t++) {
                uint32_t bb[2];
                bb[0] = vp[(kk * 8 + qid)     * VS + t * 8 + grp];
                bb[1] = vp[(kk * 8 + qid + 4) * VS + t * 8 + grp];
                mma_tf32(o[0][t], pa[0], bb);
                mma_tf32(o[1][t], pa[1], bb);
            }
        }
    }

    // ---- epilogue ----
#pragma unroll
    for (int a = 0; a < 2; a++) {
        l0[a] += __shfl_xor_sync(0xffffffffu, l0[a], 1);
        l0[a] += __shfl_xor_sync(0xffffffffu, l0[a], 2);
        l1[a] += __shfl_xor_sync(0xffffffffu, l1[a], 1);
        l1[a] += __shfl_xor_sync(0xffffffffu, l1[a], 2);
        float inv0 = 1.0f / l0[a], inv1 = 1.0f / l1[a];

        float* ob = g_attn + ((size_t)(b * S + qbase + a * 16)) * E + h * D;
#pragma unroll
        for (int t = 0; t < 8; t++) {
            int col = t * 8 + 2 * qid;
            float2 w0 = make_float2(o[a][t][0] * inv0, o[a][t][1] * inv0);
            float2 w1 = make_float2(o[a][t][2] * inv1, o[a][t][3] * inv1);
            *(float2*)&ob[(size_t)grp       * E + col] = w0;
            *(float2*)&ob[(size_t)(grp + 8) * E + col] = w1;
        }
    }
}

// ---------------------------------------------------------------------------
// Output projection, tf32 mma.sync: C[8192,1024] = g_attn @ W^T + bias.
// 128x128 tile, 128 threads / 4 warps, each warp 32 rows (2 A-tiles) so
// W B-fragments amortize over 2x rows. Grid is n-fastest for A L2 reuse.
// ---------------------------------------------------------------------------
#define PROJ_LDS 68
#define PBKC 64

__global__ void __launch_bounds__(128)
proj_mma_kernel(const float* __restrict__ W,
                const float* __restrict__ bias,
                float* __restrict__ C)
{
    extern __shared__ float smf[];
    float* As = smf;                    // [128][68]
    float* Ws = smf + 128 * PROJ_LDS;   // [128][68]

    const int tid  = threadIdx.x;
    const int warp = tid >> 5;
    const int lane = tid & 31;
    const int grp  = lane >> 2;
    const int qid  = lane & 3;

    const int n0 = blockIdx.x * 128;
    const int m0 = blockIdx.y * 128;
    const int mrow = warp * 32;

    const float* A = g_attn;

    float acc[2][16][4];
#pragma unroll
    for (int a = 0; a < 2; a++)
#pragma unroll
        for (int t = 0; t < 16; t++) { acc[a][t][0] = acc[a][t][1] = acc[a][t][2] = acc[a][t][3] = 0.f; }

    for (int k0 = 0; k0 < E; k0 += PBKC) {
        __syncthreads();
#pragma unroll
        for (int i = 0; i < 16; i++) {
            int f = i * 128 + tid;
            int row = f >> 4;              // 0..127
            int c   = (f & 15) << 2;       // 0,4,..,60
            float4 a4 = *(const float4*)&A[(size_t)(m0 + row) * E + k0 + c];
            float4 w4 = *(const float4*)&W[(size_t)(n0 + row) * E + k0 + c];
            *(uint4*)&As[row * PROJ_LDS + c] =
                make_uint4(f2tf(a4.x), f2tf(a4.y), f2tf(a4.z), f2tf(a4.w));
            *(uint4*)&Ws[row * PROJ_LDS + c] =
                make_uint4(f2tf(w4.x), f2tf(w4.y), f2tf(w4.z), f2tf(w4.w));
        }
        __syncthreads();

        const uint32_t* ap = (const uint32_t*)As;
        const uint32_t* wp = (const uint32_t*)Ws;
#pragma unroll
        for (int kk = 0; kk < 8; kk++) {
            uint32_t a[2][4];
#pragma unroll
            for (int at = 0; at < 2; at++) {
                int r = mrow + at * 16 + grp;
                a[at][0] = ap[r       * PROJ_LDS + kk * 8 + qid];
                a[at][1] = ap[(r + 8) * PROJ_LDS + kk * 8 + qid];
                a[at][2] = ap[r       * PROJ_LDS + kk * 8 + qid + 4];
                a[at][3] = ap[(r + 8) * PROJ_LDS + kk * 8 + qid + 4];
            }
#pragma unroll
            for (int t = 0; t < 16; t++) {
                uint32_t bb[2];
                bb[0] = wp[(t * 8 + grp) * PROJ_LDS + kk * 8 + qid];
                bb[1] = wp[(t * 8 + grp) * PROJ_LDS + kk * 8 + qid + 4];
                mma_tf32(acc[0][t], a[0], bb);
                mma_tf32(acc[1][t], a[1], bb);
            }
        }
    }

    // epilogue: bias + store
#pragma unroll
    for (int at = 0; at < 2; at++) {
        int rbase = m0 + mrow + at * 16;
#pragma unroll
        for (int t = 0; t < 16; t++) {
            int col = n0 + t * 8 + 2 * qid;
            float b0 = bias[col], b1 = bias[col + 1];
            float2 w0 = make_float2(acc[at][t][0] + b0, acc[at][t][1] + b1);
            float2 w1 = make_float2(acc[at][t][2] + b0, acc[at][t][3] + b1);
            *(float2*)&C[(size_t)(rbase + grp)     * E + col] = w0;
            *(float2*)&C[(size_t)(rbase + grp + 8) * E + col] = w1;
        }
    }
}

// ---------------------------------------------------------------------------
extern "C" void kernel_launch(void* const* d_in, const int* in_sizes, int n_in,
                              void* d_out, int out_size)
{
    const float* q     = (const float*)d_in[0];
    const float* k     = (const float*)d_in[1];
    const float* v     = (const float*)d_in[2];
    const float* w_out = (const float*)d_in[3];
    const float* b_out = (const float*)d_in[4];
    float* out = (float*)d_out;

    const int attn_smem = (BN * KS + BN * VS + 128 * PS) * (int)sizeof(float); // 36352
    cudaFuncSetAttribute(attn_mma_kernel,
                         cudaFuncAttributeMaxDynamicSharedMemorySize, attn_smem);

    dim3 g1(S / 128, H, B);
    attn_mma_kernel<<<g1, 128, attn_smem>>>(q, k, v);

    const int proj_smem = 2 * 128 * PROJ_LDS * (int)sizeof(float); // 69632
    cudaFuncSetAttribute(proj_mma_kernel,
                         cudaFuncAttributeMaxDynamicSharedMemorySize, proj_smem);

    dim3 g2(E / 128, (B * S) / 128);
    proj_mma_kernel<<<g2, 128, proj_smem>>>(w_out, b_out, out);
}